// round 2
// baseline (speedup 1.0000x reference)
#include <cuda_runtime.h>
#include <math.h>

#define BATCH 16
#define NCLS 80
#define NANCH 17064
#define TOPK 100
#define IMG_W_MAX 1023.0f
#define IMG_H_MAX 799.0f
#define NMS_THR 0.6f

#define NMS_TPB 1024
#define PER 17  // ceil(17064/1024)

// ---------------- scratch (device globals; no allocation allowed) ------------
__device__ float  g_scores[BATCH * NANCH];
__device__ float4 g_boxes [BATCH * NANCH];
__device__ int    g_cls   [BATCH * NANCH];

__device__ __forceinline__ float sigmoidf_(float x) {
    return 1.0f / (1.0f + expf(-x));
}

// ---------------- decode: per-anchor score / class / box ---------------------
__global__ void decode_kernel(
    const float* __restrict__ c0, const float* __restrict__ c1,
    const float* __restrict__ c2, const float* __restrict__ c3,
    const float* __restrict__ c4,
    const float* __restrict__ b0, const float* __restrict__ b1,
    const float* __restrict__ b2, const float* __restrict__ b3,
    const float* __restrict__ b4,
    const float* __restrict__ t0, const float* __restrict__ t1,
    const float* __restrict__ t2, const float* __restrict__ t3,
    const float* __restrict__ t4)
{
    int idx = blockIdx.x * blockDim.x + threadIdx.x;
    if (idx >= BATCH * NANCH) return;
    int b = idx / NANCH;
    int n = idx - b * NANCH;

    // level lookup (concat order p3..p7)
    int base, H, W, S;
    const float* cp; const float* bp; const float* tp;
    if (n < 12800)      { base = 0;     H = 100; W = 128; S = 8;   cp = c0; bp = b0; tp = t0; }
    else if (n < 16000) { base = 12800; H = 50;  W = 64;  S = 16;  cp = c1; bp = b1; tp = t1; }
    else if (n < 16800) { base = 16000; H = 25;  W = 32;  S = 32;  cp = c2; bp = b2; tp = t2; }
    else if (n < 17008) { base = 16800; H = 13;  W = 16;  S = 64;  cp = c3; bp = b3; tp = t3; }
    else                { base = 17008; H = 7;   W = 8;   S = 128; cp = c4; bp = b4; tp = t4; }

    int hw = n - base;
    int HW = H * W;

    float ctrn = sigmoidf_(tp[(size_t)b * HW + hw]);

    // argmax over comb = sigmoid(cls)*ctrn, first-index tie-break (matches jnp.argmax)
    const float* cbase = cp + (size_t)b * NCLS * HW + hw;
    float best = -INFINITY;
    int bc = 0;
    for (int c = 0; c < NCLS; c++) {
        float comb = sigmoidf_(cbase[(size_t)c * HW]) * ctrn;
        if (comb > best) { best = comb; bc = c; }
    }
    float score = sqrtf(best);

    const float* bb = bp + (size_t)b * 4 * HW + hw;
    float l = bb[0]        * (float)S;
    float t = bb[HW]       * (float)S;
    float r = bb[2 * HW]   * (float)S;
    float d = bb[3 * HW]   * (float)S;

    float px = (float)((hw % W) * S + S / 2);
    float py = (float)((hw / W) * S + S / 2);

    float x1 = fminf(fmaxf(px - l, 0.0f), IMG_W_MAX);
    float y1 = fminf(fmaxf(py - t, 0.0f), IMG_H_MAX);
    float x2 = fminf(fmaxf(px + r, 0.0f), IMG_W_MAX);
    float y2 = fminf(fmaxf(py + d, 0.0f), IMG_H_MAX);

    g_scores[idx] = score;
    g_cls[idx]    = bc;
    g_boxes[idx]  = make_float4(x1, y1, x2, y2);
}

// ---------------- zero-fill output -------------------------------------------
__global__ void zero_kernel(float* __restrict__ out, int n)
{
    int i = blockIdx.x * blockDim.x + threadIdx.x;
    if (i < n) out[i] = 0.0f;
}

// ---------------- class-aware greedy NMS, one block per image ----------------
__global__ void __launch_bounds__(NMS_TPB, 1)
nms_kernel(float* __restrict__ out, int out_size)
{
    const int b   = blockIdx.x;
    const int tid = threadIdx.x;
    const int warp = tid >> 5;
    const int lane = tid & 31;

    const float*  Sg = g_scores + (size_t)b * NANCH;
    const int*    Cg = g_cls    + (size_t)b * NANCH;
    const float4* Bg = g_boxes  + (size_t)b * NANCH;

    float sc[PER];
    int   cl[PER];
#pragma unroll
    for (int j = 0; j < PER; j++) {
        int g = tid + j * NMS_TPB;
        if (g < NANCH) { sc[j] = Sg[g]; cl[j] = Cg[g]; }
        else           { sc[j] = -INFINITY; cl[j] = -2; }
    }

    __shared__ float s_val[32];
    __shared__ int   s_idx[32];
    __shared__ float4 s_box;
    __shared__ int    s_cc, s_sel;

    const int dets_elems = BATCH * TOPK * 5;   // 8000
    const bool write_cls = (out_size >= dets_elems + BATCH * TOPK);

    for (int it = 0; it < TOPK; it++) {
        // ---- local argmax: init with first owned element so bi is always valid,
        //      strict '>' afterwards keeps lowest index on ties (matches jnp.argmax)
        float bv = sc[0];
        int   bi = tid;
#pragma unroll
        for (int j = 1; j < PER; j++) {
            if (sc[j] > bv) { bv = sc[j]; bi = tid + j * NMS_TPB; }
        }
        // ---- warp reduce (tie -> lower index)
#pragma unroll
        for (int off = 16; off; off >>= 1) {
            float ov = __shfl_down_sync(0xffffffffu, bv, off);
            int   oi = __shfl_down_sync(0xffffffffu, bi, off);
            if (ov > bv || (ov == bv && oi < bi)) { bv = ov; bi = oi; }
        }
        if (lane == 0) { s_val[warp] = bv; s_idx[warp] = bi; }
        __syncthreads();
        if (warp == 0) {
            bv = s_val[lane];
            bi = s_idx[lane];
#pragma unroll
            for (int off = 16; off; off >>= 1) {
                float ov = __shfl_down_sync(0xffffffffu, bv, off);
                int   oi = __shfl_down_sync(0xffffffffu, bi, off);
                if (ov > bv || (ov == bv && oi < bi)) { bv = ov; bi = oi; }
            }
            if (lane == 0) {
                float4 bx = Bg[bi];
                int    cc = Cg[bi];
                s_sel = bi; s_box = bx; s_cc = cc;
                // write output row
                bool valid = (bv > -INFINITY);   // == isfinite here
                int row = b * TOPK + it;
                float* dr = out + (size_t)row * 5;
                if (valid) {
                    dr[0] = bx.x; dr[1] = bx.y; dr[2] = bx.z; dr[3] = bx.w; dr[4] = bv;
                } else {
                    dr[0] = 0.0f; dr[1] = 0.0f; dr[2] = 0.0f; dr[3] = 0.0f; dr[4] = -1.0f;
                }
                if (write_cls)
                    out[dets_elems + row] = valid ? (float)cc : -1.0f;
            }
        }
        __syncthreads();

        // ---- suppression
        float4 bx = s_box;
        int   scls = s_cc;
        int   sel  = s_sel;
        float sa = (bx.z - bx.x) * (bx.w - bx.y);
#pragma unroll
        for (int j = 0; j < PER; j++) {
            int g = tid + j * NMS_TPB;
            if (g == sel) { sc[j] = -INFINITY; continue; }
            if (cl[j] != scls || sc[j] == -INFINITY) continue;
            float4 ob = Bg[g];
            float xx1 = fmaxf(bx.x, ob.x);
            float yy1 = fmaxf(bx.y, ob.y);
            float xx2 = fminf(bx.z, ob.z);
            float yy2 = fminf(bx.w, ob.w);
            float inter = fmaxf(xx2 - xx1, 0.0f) * fmaxf(yy2 - yy1, 0.0f);
            float oa = (ob.z - ob.x) * (ob.w - ob.y);
            float iou = inter / (sa + oa - inter + 1e-9f);
            if (iou > NMS_THR) sc[j] = -INFINITY;
        }
        // next iteration's shared writes are ordered by the two barriers above
    }
}

// ---------------- launch ------------------------------------------------------
extern "C" void kernel_launch(void* const* d_in, const int* in_sizes, int n_in,
                              void* d_out, int out_size)
{
    const float* c[5]; const float* bx[5]; const float* ct[5];

    // setup_inputs() builds the dict interleaved per level:
    //   cls_p3, box_p3, ctr_p3, cls_p4, box_p4, ctr_p4, ...
    // but be robust: detect grouped order (cls x5, box x5, ctr x5) via sizes.
    // interleaved: in_sizes[1] == 16*4*100*128 = 819200 (box_p3)
    // grouped:     in_sizes[1] == 16*80*50*64 = 4096000 (cls_p4)
    if (n_in >= 15 && in_sizes[1] == 819200) {
        for (int i = 0; i < 5; i++) {
            c[i]  = (const float*)d_in[3 * i + 0];
            bx[i] = (const float*)d_in[3 * i + 1];
            ct[i] = (const float*)d_in[3 * i + 2];
        }
    } else {
        for (int i = 0; i < 5; i++) {
            c[i]  = (const float*)d_in[i];
            bx[i] = (const float*)d_in[5 + i];
            ct[i] = (const float*)d_in[10 + i];
        }
    }
    float* out = (float*)d_out;

    zero_kernel<<<(out_size + 255) / 256, 256>>>(out, out_size);

    int total = BATCH * NANCH;
    decode_kernel<<<(total + 255) / 256, 256>>>(
        c[0], c[1], c[2], c[3], c[4],
        bx[0], bx[1], bx[2], bx[3], bx[4],
        ct[0], ct[1], ct[2], ct[3], ct[4]);

    nms_kernel<<<BATCH, NMS_TPB>>>(out, out_size);
}